// round 1
// baseline (speedup 1.0000x reference)
#include <cuda_runtime.h>
#include <cuda_bf16.h>
#include <cstdint>

// Problem constants
#define S_TOK   8192      // s*b = 2048*4 tokens
#define MDIM    1024
#define NEXP    8
#define FFN     4096
#define CAP     1024      // capacity = S/E

// ---------------- device scratch (static, no allocs) ----------------
__device__ int   g_expert_of_token[S_TOK];
__device__ float g_gate_of_token[S_TOK];
__device__ int   g_slot_of_token[S_TOK];        // -1 if dropped
__device__ int   g_expert_tokens[NEXP * CAP];   // token id per (e,c), -1 if empty
__device__ float g_gate_slot[NEXP * CAP];
__device__ float g_H[(size_t)NEXP * CAP * FFN]; // 128 MB hidden activations

// ---------------- K1: gating (logits, softmax, argmax) ----------------
// one warp per token; wg transposed into shared
__global__ void gate_kernel(const float* __restrict__ x, const float* __restrict__ wg) {
    __shared__ float shw[NEXP][MDIM];   // 32 KB
    int tid = threadIdx.x;
    for (int idx = tid; idx < MDIM * NEXP; idx += 256) {
        int k = idx >> 3, e = idx & 7;
        shw[e][k] = wg[idx];
    }
    __syncthreads();

    int warp = tid >> 5, lane = tid & 31;
    int s = blockIdx.x * 8 + warp;
    const float* xr = x + (size_t)s * MDIM;

    float acc[NEXP];
#pragma unroll
    for (int e = 0; e < NEXP; e++) acc[e] = 0.f;

#pragma unroll
    for (int i = 0; i < 8; i++) {
        float4 xv = *(const float4*)(xr + i * 128 + lane * 4);
#pragma unroll
        for (int e = 0; e < NEXP; e++) {
            float4 wv = *(const float4*)&shw[e][i * 128 + lane * 4];
            acc[e] += xv.x * wv.x + xv.y * wv.y + xv.z * wv.z + xv.w * wv.w;
        }
    }
#pragma unroll
    for (int e = 0; e < NEXP; e++) {
#pragma unroll
        for (int off = 16; off; off >>= 1)
            acc[e] += __shfl_xor_sync(0xffffffffu, acc[e], off);
    }
    if (lane == 0) {
        float best = acc[0]; int bi = 0;
#pragma unroll
        for (int e = 1; e < NEXP; e++) {
            if (acc[e] > best) { best = acc[e]; bi = e; }  // first-max tie rule
        }
        float sum = 0.f;
#pragma unroll
        for (int e = 0; e < NEXP; e++) sum += __expf(acc[e] - best);
        g_expert_of_token[s] = bi;
        g_gate_of_token[s]   = 1.0f / sum;  // softmax prob of argmax
        g_slot_of_token[s]   = -1;
    }
}

// ---------------- K2: per-expert deterministic rank scan ----------------
// one block per expert; 1024 threads, 8 contiguous tokens per thread
__global__ void scan_kernel() {
    int e = blockIdx.x;
    int t = threadIdx.x;

    // init slot tables for this expert
    g_expert_tokens[e * CAP + t] = -1;
    g_gate_slot[e * CAP + t] = 0.f;
    __syncthreads();

    int base = t * 8;
    int cnt = 0;
    int loc[8];
#pragma unroll
    for (int j = 0; j < 8; j++) {
        loc[j] = cnt;
        if (g_expert_of_token[base + j] == e) cnt++;
    }

    __shared__ int sh[1024];
    sh[t] = cnt;
    __syncthreads();
    for (int off = 1; off < 1024; off <<= 1) {
        int v = (t >= off) ? sh[t - off] : 0;
        __syncthreads();
        sh[t] += v;
        __syncthreads();
    }
    int excl = sh[t] - cnt;

#pragma unroll
    for (int j = 0; j < 8; j++) {
        int s = base + j;
        if (g_expert_of_token[s] == e) {
            int c = excl + loc[j];
            if (c < CAP) {
                g_expert_tokens[e * CAP + c] = s;
                g_gate_slot[e * CAP + c]     = g_gate_of_token[s];
                g_slot_of_token[s]           = c;
            }
        }
    }
}

// ---------------- tiled SGEMM helpers ----------------
#define BM 128
#define BN 128
#define BK 8
#define TM 8
#define TN 8

// GEMM1: H[e*CAP+r, :] = relu( x2d[tok(r), :] @ w1[e] ), gathered A rows
__global__ void __launch_bounds__(256) gemm1_kernel(const float* __restrict__ X,
                                                    const float* __restrict__ W1) {
    int bx = blockIdx.x;   // N tile (FFN/128 = 32)
    int by = blockIdx.y;   // M tile (E*CAP/128 = 64)
    int e  = (by * BM) / CAP;

    __shared__ float As[BK][BM];
    __shared__ float Bs[BK][BN];

    int tid  = threadIdx.x;
    int arow = tid >> 1;
    int acol = (tid & 1) * 4;
    int tok  = g_expert_tokens[by * BM + arow];
    const float* xrow = (tok >= 0) ? (X + (size_t)tok * MDIM) : nullptr;

    int brow = tid >> 5;
    int bcol = (tid & 31) * 4;
    const float* Bptr = W1 + (size_t)e * MDIM * FFN + (size_t)bx * BN;

    int tx = tid & 15, ty = tid >> 4;
    float acc[TM][TN] = {};

    for (int k0 = 0; k0 < MDIM; k0 += BK) {
        float4 av = xrow ? *(const float4*)(xrow + k0 + acol)
                         : make_float4(0.f, 0.f, 0.f, 0.f);
        float4 bv = *(const float4*)(Bptr + (size_t)(k0 + brow) * FFN + bcol);
        As[acol + 0][arow] = av.x;
        As[acol + 1][arow] = av.y;
        As[acol + 2][arow] = av.z;
        As[acol + 3][arow] = av.w;
        *(float4*)&Bs[brow][bcol] = bv;
        __syncthreads();

#pragma unroll
        for (int k = 0; k < BK; k++) {
            float a[TM], b[TN];
#pragma unroll
            for (int i = 0; i < TM; i += 4) *(float4*)&a[i] = *(float4*)&As[k][ty * TM + i];
#pragma unroll
            for (int j = 0; j < TN; j += 4) *(float4*)&b[j] = *(float4*)&Bs[k][tx * TN + j];
#pragma unroll
            for (int i = 0; i < TM; i++)
#pragma unroll
                for (int j = 0; j < TN; j++)
                    acc[i][j] += a[i] * b[j];
        }
        __syncthreads();
    }

    int grow0 = by * BM + ty * TM;
    int gcol0 = bx * BN + tx * TN;
#pragma unroll
    for (int i = 0; i < TM; i++) {
        float4 v0, v1;
        v0.x = fmaxf(acc[i][0], 0.f); v0.y = fmaxf(acc[i][1], 0.f);
        v0.z = fmaxf(acc[i][2], 0.f); v0.w = fmaxf(acc[i][3], 0.f);
        v1.x = fmaxf(acc[i][4], 0.f); v1.y = fmaxf(acc[i][5], 0.f);
        v1.z = fmaxf(acc[i][6], 0.f); v1.w = fmaxf(acc[i][7], 0.f);
        *(float4*)&g_H[(size_t)(grow0 + i) * FFN + gcol0]     = v0;
        *(float4*)&g_H[(size_t)(grow0 + i) * FFN + gcol0 + 4] = v1;
    }
}

// GEMM2: out[tok(r), :] = gate(r) * ( H[r, :] @ w2[e] ), scatter epilogue
__global__ void __launch_bounds__(256) gemm2_kernel(const float* __restrict__ W2,
                                                    float* __restrict__ out) {
    int bx = blockIdx.x;   // N tile (MDIM/128 = 8)
    int by = blockIdx.y;   // M tile (E*CAP/128 = 64)
    int e  = (by * BM) / CAP;

    __shared__ float As[BK][BM];
    __shared__ float Bs[BK][BN];

    int tid  = threadIdx.x;
    int arow = tid >> 1;
    int acol = (tid & 1) * 4;
    const float* hrow = g_H + (size_t)(by * BM + arow) * FFN;

    int brow = tid >> 5;
    int bcol = (tid & 31) * 4;
    const float* Bptr = W2 + (size_t)e * FFN * MDIM + (size_t)bx * BN;

    int tx = tid & 15, ty = tid >> 4;
    float acc[TM][TN] = {};

    for (int k0 = 0; k0 < FFN; k0 += BK) {
        float4 av = *(const float4*)(hrow + k0 + acol);
        float4 bv = *(const float4*)(Bptr + (size_t)(k0 + brow) * MDIM + bcol);
        As[acol + 0][arow] = av.x;
        As[acol + 1][arow] = av.y;
        As[acol + 2][arow] = av.z;
        As[acol + 3][arow] = av.w;
        *(float4*)&Bs[brow][bcol] = bv;
        __syncthreads();

#pragma unroll
        for (int k = 0; k < BK; k++) {
            float a[TM], b[TN];
#pragma unroll
            for (int i = 0; i < TM; i += 4) *(float4*)&a[i] = *(float4*)&As[k][ty * TM + i];
#pragma unroll
            for (int j = 0; j < TN; j += 4) *(float4*)&b[j] = *(float4*)&Bs[k][tx * TN + j];
#pragma unroll
            for (int i = 0; i < TM; i++)
#pragma unroll
                for (int j = 0; j < TN; j++)
                    acc[i][j] += a[i] * b[j];
        }
        __syncthreads();
    }

    int grow0 = by * BM + ty * TM;
    int gcol0 = bx * BN + tx * TN;
#pragma unroll
    for (int i = 0; i < TM; i++) {
        int gr  = grow0 + i;
        int tok = g_expert_tokens[gr];
        if (tok >= 0) {
            float g = g_gate_slot[gr];
            float4 v0, v1;
            v0.x = g * acc[i][0]; v0.y = g * acc[i][1];
            v0.z = g * acc[i][2]; v0.w = g * acc[i][3];
            v1.x = g * acc[i][4]; v1.y = g * acc[i][5];
            v1.z = g * acc[i][6]; v1.w = g * acc[i][7];
            *(float4*)&out[(size_t)tok * MDIM + gcol0]     = v0;
            *(float4*)&out[(size_t)tok * MDIM + gcol0 + 4] = v1;
        }
    }
}

// ---------------- K5: zero rows of dropped tokens ----------------
__global__ void zero_dropped_kernel(float* __restrict__ out) {
    int s = blockIdx.x;
    if (g_slot_of_token[s] < 0) {
        float4 z = make_float4(0.f, 0.f, 0.f, 0.f);
        ((float4*)(out + (size_t)s * MDIM))[threadIdx.x] = z;
    }
}

// ---------------- launch ----------------
extern "C" void kernel_launch(void* const* d_in, const int* in_sizes, int n_in,
                              void* d_out, int out_size) {
    const float* x  = (const float*)d_in[0];   // [2048,4,1024] -> [8192,1024]
    const float* wg = (const float*)d_in[1];   // [1024,8]
    const float* w1 = (const float*)d_in[2];   // [8,1024,4096]
    const float* w2 = (const float*)d_in[3];   // [8,4096,1024]
    float* out = (float*)d_out;                // [8192,1024]

    gate_kernel<<<S_TOK / 8, 256>>>(x, wg);
    scan_kernel<<<NEXP, 1024>>>();
    gemm1_kernel<<<dim3(FFN / BN, (NEXP * CAP) / BM), 256>>>(x, w1);
    gemm2_kernel<<<dim3(MDIM / BN, (NEXP * CAP) / BM), 256>>>(w2, out);
    zero_dropped_kernel<<<S_TOK, 256>>>(out);
}

// round 3
// speedup vs baseline: 4.8557x; 4.8557x over previous
#include <cuda_runtime.h>
#include <cstdint>
#include <cstddef>

// ---------------- problem constants ----------------
#define S_TOK   8192
#define MDIM    1024
#define NEXP    8
#define FFN     4096
#define CAP     1024

// ---------------- device scratch ----------------
__device__ int   g_expert_of_token[S_TOK];
__device__ float g_gate_of_token[S_TOK];
__device__ int   g_slot_of_token[S_TOK];
__device__ int   g_expert_tokens[NEXP * CAP];
__device__ float g_gate_slot[NEXP * CAP];
__device__ float g_xr [(size_t)S_TOK * MDIM];          // tf32-rounded x
__device__ float g_H  [(size_t)NEXP * CAP * FFN];      // hidden (tf32-rounded)
__device__ float g_w1r[(size_t)NEXP * MDIM * FFN];     // w1 rounded (same layout)
__device__ float g_w2r[(size_t)NEXP * FFN * MDIM];     // w2 rounded (same layout)

// ---------------- helpers ----------------
__device__ __forceinline__ uint32_t smem_u32(const void* p) {
    uint32_t a;
    asm("{ .reg .u64 t; cvta.to.shared.u64 t, %1; cvt.u32.u64 %0, t; }" : "=r"(a) : "l"(p));
    return a;
}
__device__ __forceinline__ float rna_tf32(float x) {
    uint32_t u;
    asm("cvt.rna.tf32.f32 %0, %1;" : "=r"(u) : "f"(x));
    return __uint_as_float(u);
}
__device__ __forceinline__ void mma_tf32(float* c, const uint32_t* a, const uint32_t* b) {
    asm volatile(
        "mma.sync.aligned.m16n8k8.row.col.f32.tf32.tf32.f32 "
        "{%0,%1,%2,%3}, {%4,%5,%6,%7}, {%8,%9}, {%0,%1,%2,%3};"
        : "+f"(c[0]), "+f"(c[1]), "+f"(c[2]), "+f"(c[3])
        : "r"(a[0]), "r"(a[1]), "r"(a[2]), "r"(a[3]), "r"(b[0]), "r"(b[1]));
}
__device__ __forceinline__ void cp16(uint32_t dst, const float* src) {
    asm volatile("cp.async.cg.shared.global [%0], [%1], 16;" :: "r"(dst), "l"(src));
}
__device__ __forceinline__ void cp16_zero(uint32_t dst, const float* src) {
    asm volatile("cp.async.cg.shared.global [%0], [%1], 16, 0;" :: "r"(dst), "l"(src));
}

// ---------------- K0a: round x to tf32 ----------------
__global__ void round_x_kernel(const float* __restrict__ x) {
    size_t i = ((size_t)blockIdx.x * 256 + threadIdx.x) * 4;
    float4 v = *(const float4*)(x + i);
    v.x = rna_tf32(v.x); v.y = rna_tf32(v.y); v.z = rna_tf32(v.z); v.w = rna_tf32(v.w);
    *(float4*)(g_xr + i) = v;
}

// ---------------- K0b: round weights to tf32 ----------------
__global__ void round_w_kernel(const float* __restrict__ src, float* __restrict__ dst) {
    size_t i = ((size_t)blockIdx.x * 256 + threadIdx.x) * 4;
    float4 v = *(const float4*)(src + i);
    v.x = rna_tf32(v.x); v.y = rna_tf32(v.y); v.z = rna_tf32(v.z); v.w = rna_tf32(v.w);
    *(float4*)(dst + i) = v;
}

// ---------------- K1: gating ----------------
__global__ void gate_kernel(const float* __restrict__ x, const float* __restrict__ wg) {
    __shared__ float shw[NEXP][MDIM];
    int tid = threadIdx.x;
    for (int idx = tid; idx < MDIM * NEXP; idx += 256) {
        int k = idx >> 3, e = idx & 7;
        shw[e][k] = wg[idx];
    }
    __syncthreads();

    int warp = tid >> 5, lane = tid & 31;
    int s = blockIdx.x * 8 + warp;
    const float* xr = x + (size_t)s * MDIM;

    float acc[NEXP];
#pragma unroll
    for (int e = 0; e < NEXP; e++) acc[e] = 0.f;
#pragma unroll
    for (int i = 0; i < 8; i++) {
        float4 xv = *(const float4*)(xr + i * 128 + lane * 4);
#pragma unroll
        for (int e = 0; e < NEXP; e++) {
            float4 wv = *(const float4*)&shw[e][i * 128 + lane * 4];
            acc[e] += xv.x * wv.x + xv.y * wv.y + xv.z * wv.z + xv.w * wv.w;
        }
    }
#pragma unroll
    for (int e = 0; e < NEXP; e++) {
#pragma unroll
        for (int off = 16; off; off >>= 1)
            acc[e] += __shfl_xor_sync(0xffffffffu, acc[e], off);
    }
    if (lane == 0) {
        float best = acc[0]; int bi = 0;
#pragma unroll
        for (int e = 1; e < NEXP; e++)
            if (acc[e] > best) { best = acc[e]; bi = e; }
        float sum = 0.f;
#pragma unroll
        for (int e = 0; e < NEXP; e++) sum += __expf(acc[e] - best);
        g_expert_of_token[s] = bi;
        g_gate_of_token[s]   = 1.0f / sum;
        g_slot_of_token[s]   = -1;
    }
}

// ---------------- K2: per-expert rank scan ----------------
__global__ void scan_kernel() {
    int e = blockIdx.x;
    int t = threadIdx.x;
    g_expert_tokens[e * CAP + t] = -1;
    g_gate_slot[e * CAP + t] = 0.f;
    __syncthreads();

    int base = t * 8;
    int cnt = 0;
    int loc[8];
#pragma unroll
    for (int j = 0; j < 8; j++) {
        loc[j] = cnt;
        if (g_expert_of_token[base + j] == e) cnt++;
    }
    __shared__ int sh[1024];
    sh[t] = cnt;
    __syncthreads();
    for (int off = 1; off < 1024; off <<= 1) {
        int v = (t >= off) ? sh[t - off] : 0;
        __syncthreads();
        sh[t] += v;
        __syncthreads();
    }
    int excl = sh[t] - cnt;
#pragma unroll
    for (int j = 0; j < 8; j++) {
        int s = base + j;
        if (g_expert_of_token[s] == e) {
            int c = excl + loc[j];
            if (c < CAP) {
                g_expert_tokens[e * CAP + c] = s;
                g_gate_slot[e * CAP + c]     = g_gate_of_token[s];
                g_slot_of_token[s]           = c;
            }
        }
    }
}

// ---------------- K3: tf32 mma.sync GEMM ----------------
// C tile 128x128, BK=16, 8 warps (4 along M, 2 along N), warp tile 32x64.
// A[m,k] row-major in SMEM [128][20] (padded). B[k,n] row-major in SMEM [16][136].
#define BM 128
#define BN 128
#define BK 16
#define APAD 20
#define BPAD 136

template<int K_TOTAL, int NDIM, bool IS_G2>
__global__ void __launch_bounds__(256) mma_gemm(float* __restrict__ OUT) {
    constexpr int CITER = K_TOTAL / BK;
    __shared__ float As[2][BM][APAD];
    __shared__ float Bs[2][BK][BPAD];

    int tid = threadIdx.x;
    int wid = tid >> 5, lane = tid & 31;
    int wm = wid & 3, wn = wid >> 2;
    int g = lane >> 2, tg = lane & 3;

    int m0 = blockIdx.y * BM;
    int n0 = blockIdx.x * BN;
    int e  = m0 >> 10;

    const float* Bw = (IS_G2 ? g_w2r : g_w1r) + (size_t)e * ((size_t)MDIM * FFN);

    // --- A loads: 512 chunks of 16B (128 rows x 4), 2 per thread ---
    const float* srcA[2];
    uint32_t dstA[2][2];
#pragma unroll
    for (int i = 0; i < 2; i++) {
        int idx = tid + i * 256;
        int r = idx >> 2, ch = idx & 3;
        dstA[i][0] = smem_u32(&As[0][r][ch * 4]);
        dstA[i][1] = smem_u32(&As[1][r][ch * 4]);
        const float* p;
        if (IS_G2) p = &g_H[(size_t)(m0 + r) * FFN];
        else {
            int tok = g_expert_tokens[m0 + r];
            p = (tok >= 0) ? &g_xr[(size_t)tok * MDIM] : nullptr;
        }
        srcA[i] = p ? (p + ch * 4) : nullptr;
    }
    // --- B loads: 512 chunks (16 rows x 32), 2 per thread ---
    const float* srcB[2];
    uint32_t dstB[2][2];
#pragma unroll
    for (int i = 0; i < 2; i++) {
        int idx = tid + i * 256;
        int r = idx >> 5, ch = idx & 31;
        dstB[i][0] = smem_u32(&Bs[0][r][ch * 4]);
        dstB[i][1] = smem_u32(&Bs[1][r][ch * 4]);
        srcB[i] = Bw + (size_t)r * NDIM + n0 + ch * 4;
    }

    auto load_stage = [&](int s, int k0) {
#pragma unroll
        for (int i = 0; i < 2; i++) {
            if (srcA[i]) cp16(dstA[i][s], srcA[i] + k0);
            else         cp16_zero(dstA[i][s], Bw);
        }
#pragma unroll
        for (int i = 0; i < 2; i++)
            cp16(dstB[i][s], srcB[i] + (size_t)k0 * NDIM);
        asm volatile("cp.async.commit_group;" ::: "memory");
    };

    load_stage(0, 0);
    load_stage(1, BK);

    float acc[2][8][4];
#pragma unroll
    for (int mi = 0; mi < 2; mi++)
#pragma unroll
        for (int ni = 0; ni < 8; ni++)
#pragma unroll
            for (int q = 0; q < 4; q++) acc[mi][ni][q] = 0.f;

    for (int c = 0; c < CITER; c++) {
        int s = c & 1;
        if (c + 1 < CITER) asm volatile("cp.async.wait_group 1;" ::: "memory");
        else               asm volatile("cp.async.wait_group 0;" ::: "memory");
        __syncthreads();

#pragma unroll
        for (int kk = 0; kk < 2; kk++) {
            int kb = kk * 8;
            uint32_t af[2][4];
#pragma unroll
            for (int mi = 0; mi < 2; mi++) {
                int r = wm * 32 + mi * 16 + g;
                af[mi][0] = __float_as_uint(As[s][r    ][kb + tg]);
                af[mi][1] = __float_as_uint(As[s][r + 8][kb + tg]);
                af[mi][2] = __float_as_uint(As[s][r    ][kb + tg + 4]);
                af[mi][3] = __float_as_uint(As[s][r + 8][kb + tg + 4]);
            }
            uint32_t bf[8][2];
#pragma unroll
            for (int ni = 0; ni < 8; ni++) {
                int cc = wn * 64 + ni * 8 + g;
                bf[ni][0] = __float_as_uint(Bs[s][kb + tg    ][cc]);
                bf[ni][1] = __float_as_uint(Bs[s][kb + tg + 4][cc]);
            }
#pragma unroll
            for (int mi = 0; mi < 2; mi++)
#pragma unroll
                for (int ni = 0; ni < 8; ni++)
                    mma_tf32(acc[mi][ni], af[mi], bf[ni]);
        }

        if (c + 2 < CITER) {
            __syncthreads();
            load_stage(s, (c + 2) * BK);
        }
    }

    // ---------------- epilogue ----------------
    if (!IS_G2) {
#pragma unroll
        for (int mi = 0; mi < 2; mi++) {
            int r0 = m0 + wm * 32 + mi * 16 + g;
#pragma unroll
            for (int ni = 0; ni < 8; ni++) {
                int cc = n0 + wn * 64 + ni * 8 + 2 * tg;
                float2 v0, v1;
                v0.x = rna_tf32(fmaxf(acc[mi][ni][0], 0.f));
                v0.y = rna_tf32(fmaxf(acc[mi][ni][1], 0.f));
                v1.x = rna_tf32(fmaxf(acc[mi][ni][2], 0.f));
                v1.y = rna_tf32(fmaxf(acc[mi][ni][3], 0.f));
                *(float2*)&g_H[(size_t)r0 * FFN + cc]       = v0;
                *(float2*)&g_H[(size_t)(r0 + 8) * FFN + cc] = v1;
            }
        }
    } else {
#pragma unroll
        for (int mi = 0; mi < 2; mi++) {
            int r0 = m0 + wm * 32 + mi * 16 + g;
            int tokA = g_expert_tokens[r0];
            int tokB = g_expert_tokens[r0 + 8];
            float gA = g_gate_slot[r0];
            float gB = g_gate_slot[r0 + 8];
#pragma unroll
            for (int ni = 0; ni < 8; ni++) {
                int cc = n0 + wn * 64 + ni * 8 + 2 * tg;
                if (tokA >= 0) {
                    float2 v; v.x = gA * acc[mi][ni][0]; v.y = gA * acc[mi][ni][1];
                    *(float2*)&OUT[(size_t)tokA * MDIM + cc] = v;
                }
                if (tokB >= 0) {
                    float2 v; v.x = gB * acc[mi][ni][2]; v.y = gB * acc[mi][ni][3];
                    *(float2*)&OUT[(size_t)tokB * MDIM + cc] = v;
                }
            }
        }
    }
}

// ---------------- K5: zero dropped-token rows ----------------
__global__ void zero_dropped_kernel(float* __restrict__ out) {
    int s = blockIdx.x;
    if (g_slot_of_token[s] < 0) {
        float4 z = make_float4(0.f, 0.f, 0.f, 0.f);
        ((float4*)(out + (size_t)s * MDIM))[threadIdx.x] = z;
    }
}

// ---------------- launch ----------------
extern "C" void kernel_launch(void* const* d_in, const int* in_sizes, int n_in,
                              void* d_out, int out_size) {
    const float* x  = (const float*)d_in[0];
    const float* wg = (const float*)d_in[1];
    const float* w1 = (const float*)d_in[2];
    const float* w2 = (const float*)d_in[3];
    float* out = (float*)d_out;

    round_x_kernel<<<S_TOK * MDIM / 1024, 256>>>(x);
    float* w1r; cudaGetSymbolAddress((void**)&w1r, g_w1r);
    float* w2r; cudaGetSymbolAddress((void**)&w2r, g_w2r);
    round_w_kernel<<<(size_t)NEXP * MDIM * FFN / 1024, 256>>>(w1, w1r);
    round_w_kernel<<<(size_t)NEXP * FFN * MDIM / 1024, 256>>>(w2, w2r);

    gate_kernel<<<S_TOK / 8, 256>>>(x, wg);
    scan_kernel<<<NEXP, 1024>>>();

    mma_gemm<MDIM, FFN,  false><<<dim3(FFN / BN,  (NEXP * CAP) / BM), 256>>>(nullptr);
    mma_gemm<FFN,  MDIM, true ><<<dim3(MDIM / BN, (NEXP * CAP) / BM), 256>>>(out);

    zero_dropped_kernel<<<S_TOK, 256>>>(out);
}

// round 4
// speedup vs baseline: 5.1442x; 1.0594x over previous
#include <cuda_runtime.h>
#include <cstdint>
#include <cstddef>

// ---------------- problem constants ----------------
#define S_TOK   8192
#define MDIM    1024
#define NEXP    8
#define FFN     4096
#define CAP     1024

// ---------------- device scratch ----------------
__device__ int   g_expert_of_token[S_TOK];
__device__ float g_gate_of_token[S_TOK];
__device__ int   g_slot_of_token[S_TOK];
__device__ int   g_expert_tokens[NEXP * CAP];
__device__ float g_gate_slot[NEXP * CAP];
__device__ float g_H[(size_t)NEXP * CAP * FFN];   // hidden (tf32-rounded at write)

// ---------------- helpers ----------------
__device__ __forceinline__ uint32_t smem_u32(const void* p) {
    uint32_t a;
    asm("{ .reg .u64 t; cvta.to.shared.u64 t, %1; cvt.u32.u64 %0, t; }" : "=r"(a) : "l"(p));
    return a;
}
__device__ __forceinline__ float rna_tf32(float x) {
    uint32_t u;
    asm("cvt.rna.tf32.f32 %0, %1;" : "=r"(u) : "f"(x));
    return __uint_as_float(u);
}
__device__ __forceinline__ uint32_t rna_tf32_u(float x) {
    uint32_t u;
    asm("cvt.rna.tf32.f32 %0, %1;" : "=r"(u) : "f"(x));
    return u;
}
__device__ __forceinline__ void mma_tf32(float* c, const uint32_t* a, const uint32_t* b) {
    asm volatile(
        "mma.sync.aligned.m16n8k8.row.col.f32.tf32.tf32.f32 "
        "{%0,%1,%2,%3}, {%4,%5,%6,%7}, {%8,%9}, {%0,%1,%2,%3};"
        : "+f"(c[0]), "+f"(c[1]), "+f"(c[2]), "+f"(c[3])
        : "r"(a[0]), "r"(a[1]), "r"(a[2]), "r"(a[3]), "r"(b[0]), "r"(b[1]));
}
__device__ __forceinline__ void cp16(uint32_t dst, const float* src) {
    asm volatile("cp.async.cg.shared.global [%0], [%1], 16;" :: "r"(dst), "l"(src));
}
__device__ __forceinline__ void cp16_zero(uint32_t dst, const float* src) {
    asm volatile("cp.async.cg.shared.global [%0], [%1], 16, 0;" :: "r"(dst), "l"(src));
}

// ---------------- K1: gating ----------------
__global__ void gate_kernel(const float* __restrict__ x, const float* __restrict__ wg) {
    __shared__ float shw[NEXP][MDIM];
    int tid = threadIdx.x;
    for (int idx = tid; idx < MDIM * NEXP; idx += 256) {
        int k = idx >> 3, e = idx & 7;
        shw[e][k] = wg[idx];
    }
    __syncthreads();

    int warp = tid >> 5, lane = tid & 31;
    int s = blockIdx.x * 8 + warp;
    const float* xr = x + (size_t)s * MDIM;

    float acc[NEXP];
#pragma unroll
    for (int e = 0; e < NEXP; e++) acc[e] = 0.f;
#pragma unroll
    for (int i = 0; i < 8; i++) {
        float4 xv = *(const float4*)(xr + i * 128 + lane * 4);
#pragma unroll
        for (int e = 0; e < NEXP; e++) {
            float4 wv = *(const float4*)&shw[e][i * 128 + lane * 4];
            acc[e] += xv.x * wv.x + xv.y * wv.y + xv.z * wv.z + xv.w * wv.w;
        }
    }
#pragma unroll
    for (int e = 0; e < NEXP; e++) {
#pragma unroll
        for (int off = 16; off; off >>= 1)
            acc[e] += __shfl_xor_sync(0xffffffffu, acc[e], off);
    }
    if (lane == 0) {
        float best = acc[0]; int bi = 0;
#pragma unroll
        for (int e = 1; e < NEXP; e++)
            if (acc[e] > best) { best = acc[e]; bi = e; }
        float sum = 0.f;
#pragma unroll
        for (int e = 0; e < NEXP; e++) sum += __expf(acc[e] - best);
        g_expert_of_token[s] = bi;
        g_gate_of_token[s]   = 1.0f / sum;
        g_slot_of_token[s]   = -1;
    }
}

// ---------------- K2: per-expert rank scan ----------------
__global__ void scan_kernel() {
    int e = blockIdx.x;
    int t = threadIdx.x;
    g_expert_tokens[e * CAP + t] = -1;
    g_gate_slot[e * CAP + t] = 0.f;
    __syncthreads();

    int base = t * 8;
    int cnt = 0;
    int loc[8];
#pragma unroll
    for (int j = 0; j < 8; j++) {
        loc[j] = cnt;
        if (g_expert_of_token[base + j] == e) cnt++;
    }
    __shared__ int sh[1024];
    sh[t] = cnt;
    __syncthreads();
    for (int off = 1; off < 1024; off <<= 1) {
        int v = (t >= off) ? sh[t - off] : 0;
        __syncthreads();
        sh[t] += v;
        __syncthreads();
    }
    int excl = sh[t] - cnt;
#pragma unroll
    for (int j = 0; j < 8; j++) {
        int s = base + j;
        if (g_expert_of_token[s] == e) {
            int c = excl + loc[j];
            if (c < CAP) {
                g_expert_tokens[e * CAP + c] = s;
                g_gate_slot[e * CAP + c]     = g_gate_of_token[s];
                g_slot_of_token[s]           = c;
            }
        }
    }
}

// ---------------- K3: tf32 mma.sync GEMM ----------------
// C tile 128x128, BK=16, 8 warps (4 M x 2 N), warp tile 32x64.
// 4-stage cp.async ring in dynamic SMEM, ONE __syncthreads per k-chunk.
// A[m,k] SMEM [128][20] padded, B[k,n] SMEM [16][136] padded (conflict-free).
#define BM 128
#define BN 128
#define BK 16
#define APAD 20
#define BPAD 136
#define NSTAGE 4
#define A_FLOATS (BM * APAD)             // 2560
#define STAGE_B  ((BM * APAD + BK * BPAD) * 4)   // 18944 bytes
#define GEMM_SMEM (NSTAGE * STAGE_B)

template<int K_TOTAL, int NDIM, bool IS_G2>
__global__ void __launch_bounds__(256) mma_gemm(const float* __restrict__ Xin,
                                                const float* __restrict__ W,
                                                float* __restrict__ OUT) {
    constexpr int CITER = K_TOTAL / BK;
    extern __shared__ char smraw[];
    uint32_t sbase = smem_u32(smraw);

    int tid = threadIdx.x;
    int wid = tid >> 5, lane = tid & 31;
    int wm = wid & 3, wn = wid >> 2;
    int g = lane >> 2, tg = lane & 3;

    int m0 = blockIdx.y * BM;
    int n0 = blockIdx.x * BN;
    int e  = m0 >> 10;

    const float* Bw = W + (size_t)e * ((size_t)MDIM * FFN);

    // --- A loads: 512 chunks of 16B (128 rows x 4 chunks), 2 per thread ---
    const float* srcA[2];
    uint32_t offA[2];
#pragma unroll
    for (int i = 0; i < 2; i++) {
        int idx = tid + i * 256;
        int r = idx >> 2, ch = idx & 3;
        offA[i] = (uint32_t)(r * APAD + ch * 4) * 4u;
        const float* p;
        if (IS_G2) p = &g_H[(size_t)(m0 + r) * FFN];
        else {
            int tok = g_expert_tokens[m0 + r];
            p = (tok >= 0) ? (Xin + (size_t)tok * MDIM) : nullptr;
        }
        srcA[i] = p ? (p + ch * 4) : nullptr;
    }
    // --- B loads: 512 chunks (16 rows x 32 chunks), 2 per thread ---
    const float* srcB[2];
    uint32_t offB[2];
#pragma unroll
    for (int i = 0; i < 2; i++) {
        int idx = tid + i * 256;
        int r = idx >> 5, ch = idx & 31;
        offB[i] = (uint32_t)(A_FLOATS + r * BPAD + ch * 4) * 4u;
        srcB[i] = Bw + (size_t)r * NDIM + n0 + ch * 4;
    }

    auto load_stage = [&](int s, int k0) {
        uint32_t sb = sbase + (uint32_t)s * STAGE_B;
#pragma unroll
        for (int i = 0; i < 2; i++) {
            if (srcA[i]) cp16(sb + offA[i], srcA[i] + k0);
            else         cp16_zero(sb + offA[i], Bw);
        }
#pragma unroll
        for (int i = 0; i < 2; i++)
            cp16(sb + offB[i], srcB[i] + (size_t)k0 * NDIM);
        asm volatile("cp.async.commit_group;" ::: "memory");
    };

    // preload 3 stages
    load_stage(0, 0);
    load_stage(1, BK);
    load_stage(2, 2 * BK);

    float acc[2][8][4];
#pragma unroll
    for (int mi = 0; mi < 2; mi++)
#pragma unroll
        for (int ni = 0; ni < 8; ni++)
#pragma unroll
            for (int q = 0; q < 4; q++) acc[mi][ni][q] = 0.f;

    for (int c = 0; c < CITER; c++) {
        int s = c & (NSTAGE - 1);
        int rem = CITER - 1 - c;   // prefetched groups still ahead of this one
        if (rem >= 2)      asm volatile("cp.async.wait_group 2;" ::: "memory");
        else if (rem == 1) asm volatile("cp.async.wait_group 1;" ::: "memory");
        else               asm volatile("cp.async.wait_group 0;" ::: "memory");
        __syncthreads();   // stage c visible to all; all warps done with stage c-1

        if (c + 3 < CITER) load_stage((c + 3) & (NSTAGE - 1), (c + 3) * BK);

        const float* As = (const float*)(smraw + (size_t)s * STAGE_B);
        const float* Bs = As + A_FLOATS;

#pragma unroll
        for (int kk = 0; kk < 2; kk++) {
            int kb = kk * 8;
            uint32_t af[2][4];
#pragma unroll
            for (int mi = 0; mi < 2; mi++) {
                int r = wm * 32 + mi * 16 + g;
                float a0 = As[r * APAD + kb + tg];
                float a1 = As[(r + 8) * APAD + kb + tg];
                float a2 = As[r * APAD + kb + tg + 4];
                float a3 = As[(r + 8) * APAD + kb + tg + 4];
                if (!IS_G2) {   // x is raw fp32: round to tf32 (g_H is pre-rounded)
                    af[mi][0] = rna_tf32_u(a0); af[mi][1] = rna_tf32_u(a1);
                    af[mi][2] = rna_tf32_u(a2); af[mi][3] = rna_tf32_u(a3);
                } else {
                    af[mi][0] = __float_as_uint(a0); af[mi][1] = __float_as_uint(a1);
                    af[mi][2] = __float_as_uint(a2); af[mi][3] = __float_as_uint(a3);
                }
            }
            uint32_t bf[8][2];
#pragma unroll
            for (int ni = 0; ni < 8; ni++) {
                int cc = wn * 64 + ni * 8 + g;
                bf[ni][0] = rna_tf32_u(Bs[(kb + tg) * BPAD + cc]);
                bf[ni][1] = rna_tf32_u(Bs[(kb + tg + 4) * BPAD + cc]);
            }
#pragma unroll
            for (int mi = 0; mi < 2; mi++)
#pragma unroll
                for (int ni = 0; ni < 8; ni++)
                    mma_tf32(acc[mi][ni], af[mi], bf[ni]);
        }
    }

    // ---------------- epilogue ----------------
    if (!IS_G2) {
#pragma unroll
        for (int mi = 0; mi < 2; mi++) {
            int r0 = m0 + wm * 32 + mi * 16 + g;
#pragma unroll
            for (int ni = 0; ni < 8; ni++) {
                int cc = n0 + wn * 64 + ni * 8 + 2 * tg;
                float2 v0, v1;
                v0.x = rna_tf32(fmaxf(acc[mi][ni][0], 0.f));
                v0.y = rna_tf32(fmaxf(acc[mi][ni][1], 0.f));
                v1.x = rna_tf32(fmaxf(acc[mi][ni][2], 0.f));
                v1.y = rna_tf32(fmaxf(acc[mi][ni][3], 0.f));
                *(float2*)&g_H[(size_t)r0 * FFN + cc]       = v0;
                *(float2*)&g_H[(size_t)(r0 + 8) * FFN + cc] = v1;
            }
        }
    } else {
#pragma unroll
        for (int mi = 0; mi < 2; mi++) {
            int r0 = m0 + wm * 32 + mi * 16 + g;
            int tokA = g_expert_tokens[r0];
            int tokB = g_expert_tokens[r0 + 8];
            float gA = g_gate_slot[r0];
            float gB = g_gate_slot[r0 + 8];
#pragma unroll
            for (int ni = 0; ni < 8; ni++) {
                int cc = n0 + wn * 64 + ni * 8 + 2 * tg;
                if (tokA >= 0) {
                    float2 v; v.x = gA * acc[mi][ni][0]; v.y = gA * acc[mi][ni][1];
                    *(float2*)&OUT[(size_t)tokA * MDIM + cc] = v;
                }
                if (tokB >= 0) {
                    float2 v; v.x = gB * acc[mi][ni][2]; v.y = gB * acc[mi][ni][3];
                    *(float2*)&OUT[(size_t)tokB * MDIM + cc] = v;
                }
            }
        }
    }
}

// ---------------- K5: zero dropped-token rows ----------------
__global__ void zero_dropped_kernel(float* __restrict__ out) {
    int s = blockIdx.x;
    if (g_slot_of_token[s] < 0) {
        float4 z = make_float4(0.f, 0.f, 0.f, 0.f);
        ((float4*)(out + (size_t)s * MDIM))[threadIdx.x] = z;
    }
}

// ---------------- launch ----------------
extern "C" void kernel_launch(void* const* d_in, const int* in_sizes, int n_in,
                              void* d_out, int out_size) {
    const float* x  = (const float*)d_in[0];
    const float* wg = (const float*)d_in[1];
    const float* w1 = (const float*)d_in[2];
    const float* w2 = (const float*)d_in[3];
    float* out = (float*)d_out;

    static bool attr_done = false;
    if (!attr_done) {
        cudaFuncSetAttribute(mma_gemm<MDIM, FFN,  false>,
                             cudaFuncAttributeMaxDynamicSharedMemorySize, GEMM_SMEM);
        cudaFuncSetAttribute(mma_gemm<FFN,  MDIM, true>,
                             cudaFuncAttributeMaxDynamicSharedMemorySize, GEMM_SMEM);
        attr_done = true;
    }

    gate_kernel<<<S_TOK / 8, 256>>>(x, wg);
    scan_kernel<<<NEXP, 1024>>>();

    mma_gemm<MDIM, FFN,  false><<<dim3(FFN / BN,  (NEXP * CAP) / BM), 256, GEMM_SMEM>>>(x,  w1, nullptr);
    mma_gemm<FFN,  MDIM, true ><<<dim3(MDIM / BN, (NEXP * CAP) / BM), 256, GEMM_SMEM>>>(x,  w2, out);

    zero_dropped_kernel<<<S_TOK, 256>>>(out);
}

// round 5
// speedup vs baseline: 5.5865x; 1.0860x over previous
#include <cuda_runtime.h>
#include <cstdint>
#include <cstddef>

// ---------------- problem constants ----------------
#define S_TOK   8192
#define MDIM    1024
#define NEXP    8
#define FFN     4096
#define CAP     1024

// ---------------- device scratch ----------------
__device__ int   g_expert_of_token[S_TOK];
__device__ float g_gate_of_token[S_TOK];
__device__ int   g_slot_of_token[S_TOK];
__device__ int   g_expert_tokens[NEXP * CAP];
__device__ float g_gate_slot[NEXP * CAP];
__device__ float g_H[(size_t)NEXP * CAP * FFN];   // hidden (tf32-rounded at write)

// ---------------- helpers ----------------
__device__ __forceinline__ uint32_t smem_u32(const void* p) {
    uint32_t a;
    asm("{ .reg .u64 t; cvta.to.shared.u64 t, %1; cvt.u32.u64 %0, t; }" : "=r"(a) : "l"(p));
    return a;
}
__device__ __forceinline__ float rna_tf32(float x) {
    uint32_t u;
    asm("cvt.rna.tf32.f32 %0, %1;" : "=r"(u) : "f"(x));
    return __uint_as_float(u);
}
__device__ __forceinline__ uint32_t rna_tf32_u(float x) {
    uint32_t u;
    asm("cvt.rna.tf32.f32 %0, %1;" : "=r"(u) : "f"(x));
    return u;
}
__device__ __forceinline__ void mma_tf32(float* c, const uint32_t* a, const uint32_t* b) {
    asm volatile(
        "mma.sync.aligned.m16n8k8.row.col.f32.tf32.tf32.f32 "
        "{%0,%1,%2,%3}, {%4,%5,%6,%7}, {%8,%9}, {%0,%1,%2,%3};"
        : "+f"(c[0]), "+f"(c[1]), "+f"(c[2]), "+f"(c[3])
        : "r"(a[0]), "r"(a[1]), "r"(a[2]), "r"(a[3]), "r"(b[0]), "r"(b[1]));
}
__device__ __forceinline__ void cp16(uint32_t dst, const float* src) {
    asm volatile("cp.async.cg.shared.global [%0], [%1], 16;" :: "r"(dst), "l"(src));
}
__device__ __forceinline__ void cp16_zero(uint32_t dst, const float* src) {
    asm volatile("cp.async.cg.shared.global [%0], [%1], 16, 0;" :: "r"(dst), "l"(src));
}

// ---------------- K1: gating ----------------
__global__ void gate_kernel(const float* __restrict__ x, const float* __restrict__ wg) {
    __shared__ float shw[NEXP][MDIM];
    int tid = threadIdx.x;
    for (int idx = tid; idx < MDIM * NEXP; idx += 256) {
        int k = idx >> 3, e = idx & 7;
        shw[e][k] = wg[idx];
    }
    __syncthreads();

    int warp = tid >> 5, lane = tid & 31;
    int s = blockIdx.x * 8 + warp;
    const float* xr = x + (size_t)s * MDIM;

    float acc[NEXP];
#pragma unroll
    for (int e = 0; e < NEXP; e++) acc[e] = 0.f;
#pragma unroll
    for (int i = 0; i < 8; i++) {
        float4 xv = *(const float4*)(xr + i * 128 + lane * 4);
#pragma unroll
        for (int e = 0; e < NEXP; e++) {
            float4 wv = *(const float4*)&shw[e][i * 128 + lane * 4];
            acc[e] += xv.x * wv.x + xv.y * wv.y + xv.z * wv.z + xv.w * wv.w;
        }
    }
#pragma unroll
    for (int e = 0; e < NEXP; e++) {
#pragma unroll
        for (int off = 16; off; off >>= 1)
            acc[e] += __shfl_xor_sync(0xffffffffu, acc[e], off);
    }
    if (lane == 0) {
        float best = acc[0]; int bi = 0;
#pragma unroll
        for (int e = 1; e < NEXP; e++)
            if (acc[e] > best) { best = acc[e]; bi = e; }
        float sum = 0.f;
#pragma unroll
        for (int e = 0; e < NEXP; e++) sum += __expf(acc[e] - best);
        g_expert_of_token[s] = bi;
        g_gate_of_token[s]   = 1.0f / sum;
        g_slot_of_token[s]   = -1;
    }
}

// ---------------- K2: per-expert rank scan ----------------
__global__ void scan_kernel() {
    int e = blockIdx.x;
    int t = threadIdx.x;
    g_expert_tokens[e * CAP + t] = -1;
    g_gate_slot[e * CAP + t] = 0.f;
    __syncthreads();

    int base = t * 8;
    int cnt = 0;
    int loc[8];
#pragma unroll
    for (int j = 0; j < 8; j++) {
        loc[j] = cnt;
        if (g_expert_of_token[base + j] == e) cnt++;
    }
    __shared__ int sh[1024];
    sh[t] = cnt;
    __syncthreads();
    for (int off = 1; off < 1024; off <<= 1) {
        int v = (t >= off) ? sh[t - off] : 0;
        __syncthreads();
        sh[t] += v;
        __syncthreads();
    }
    int excl = sh[t] - cnt;
#pragma unroll
    for (int j = 0; j < 8; j++) {
        int s = base + j;
        if (g_expert_of_token[s] == e) {
            int c = excl + loc[j];
            if (c < CAP) {
                g_expert_tokens[e * CAP + c] = s;
                g_gate_slot[e * CAP + c]     = g_gate_of_token[s];
                g_slot_of_token[s]           = c;
            }
        }
    }
}

// ---------------- K3: tf32 mma.sync GEMM ----------------
// C tile 128x128, BK=32, 8 warps (4 M x 2 N), warp tile 32x64.
// 3-stage cp.async ring in dynamic SMEM, ONE __syncthreads per 32-wide k-chunk.
// A[m,k] SMEM [128][36] padded, B[k,n] SMEM [32][136] padded (both conflict-free).
#define BM 128
#define BN 128
#define BK 32
#define APAD 36
#define BPAD 136
#define NSTAGE 3
#define A_FLOATS (BM * APAD)                       // 4608
#define STAGE_B  ((BM * APAD + BK * BPAD) * 4)     // 35840 bytes
#define GEMM_SMEM (NSTAGE * STAGE_B)               // 107520

template<int K_TOTAL, int NDIM, bool IS_G2>
__global__ void __launch_bounds__(256, 2) mma_gemm(const float* __restrict__ Xin,
                                                   const float* __restrict__ W,
                                                   float* __restrict__ OUT) {
    constexpr int CITER = K_TOTAL / BK;
    extern __shared__ char smraw[];
    uint32_t sbase = smem_u32(smraw);

    int tid = threadIdx.x;
    int wid = tid >> 5, lane = tid & 31;
    int wm = wid & 3, wn = wid >> 2;
    int g = lane >> 2, tg = lane & 3;

    int m0 = blockIdx.y * BM;
    int n0 = blockIdx.x * BN;
    int e  = m0 >> 10;

    const float* Bw = W + (size_t)e * ((size_t)MDIM * FFN);

    // --- A loads: 1024 chunks of 16B (128 rows x 8 chunks), 4 per thread ---
    const float* srcA[4];
    uint32_t offA[4];
#pragma unroll
    for (int i = 0; i < 4; i++) {
        int idx = tid + i * 256;
        int r = idx >> 3, ch = idx & 7;
        offA[i] = (uint32_t)(r * APAD + ch * 4) * 4u;
        const float* p;
        if (IS_G2) p = &g_H[(size_t)(m0 + r) * FFN];
        else {
            int tok = g_expert_tokens[m0 + r];
            p = (tok >= 0) ? (Xin + (size_t)tok * MDIM) : nullptr;
        }
        srcA[i] = p ? (p + ch * 4) : nullptr;
    }
    // --- B loads: 1024 chunks (32 rows x 32 chunks), 4 per thread ---
    const float* srcB[4];
    uint32_t offB[4];
#pragma unroll
    for (int i = 0; i < 4; i++) {
        int idx = tid + i * 256;
        int r = idx >> 5, ch = idx & 31;
        offB[i] = (uint32_t)(A_FLOATS + r * BPAD + ch * 4) * 4u;
        srcB[i] = Bw + (size_t)r * NDIM + n0 + ch * 4;
    }

    auto load_stage = [&](int s, int k0) {
        uint32_t sb = sbase + (uint32_t)s * STAGE_B;
#pragma unroll
        for (int i = 0; i < 4; i++) {
            if (srcA[i]) cp16(sb + offA[i], srcA[i] + k0);
            else         cp16_zero(sb + offA[i], Bw);
        }
#pragma unroll
        for (int i = 0; i < 4; i++)
            cp16(sb + offB[i], srcB[i] + (size_t)k0 * NDIM);
        asm volatile("cp.async.commit_group;" ::: "memory");
    };

    // preload 2 stages
    load_stage(0, 0);
    load_stage(1, BK);

    float acc[2][8][4];
#pragma unroll
    for (int mi = 0; mi < 2; mi++)
#pragma unroll
        for (int ni = 0; ni < 8; ni++)
#pragma unroll
            for (int q = 0; q < 4; q++) acc[mi][ni][q] = 0.f;

    int stage = 0;
    for (int c = 0; c < CITER; c++) {
        if (c + 1 < CITER) asm volatile("cp.async.wait_group 1;" ::: "memory");
        else               asm volatile("cp.async.wait_group 0;" ::: "memory");
        __syncthreads();   // stage c visible; all warps done with stage c-1

        int pf = stage + 2; if (pf >= NSTAGE) pf -= NSTAGE;
        if (c + 2 < CITER) load_stage(pf, (c + 2) * BK);

        const float* As = (const float*)(smraw + (size_t)stage * STAGE_B);
        const float* Bs = As + A_FLOATS;

#pragma unroll
        for (int kk = 0; kk < 4; kk++) {
            int kb = kk * 8;
            uint32_t af[2][4];
#pragma unroll
            for (int mi = 0; mi < 2; mi++) {
                int r = wm * 32 + mi * 16 + g;
                float a0 = As[r * APAD + kb + tg];
                float a1 = As[(r + 8) * APAD + kb + tg];
                float a2 = As[r * APAD + kb + tg + 4];
                float a3 = As[(r + 8) * APAD + kb + tg + 4];
                if (!IS_G2) {   // x raw fp32 -> round; g_H pre-rounded
                    af[mi][0] = rna_tf32_u(a0); af[mi][1] = rna_tf32_u(a1);
                    af[mi][2] = rna_tf32_u(a2); af[mi][3] = rna_tf32_u(a3);
                } else {
                    af[mi][0] = __float_as_uint(a0); af[mi][1] = __float_as_uint(a1);
                    af[mi][2] = __float_as_uint(a2); af[mi][3] = __float_as_uint(a3);
                }
            }
            uint32_t bf[8][2];
#pragma unroll
            for (int ni = 0; ni < 8; ni++) {
                int cc = wn * 64 + ni * 8 + g;
                bf[ni][0] = rna_tf32_u(Bs[(kb + tg) * BPAD + cc]);
                bf[ni][1] = rna_tf32_u(Bs[(kb + tg + 4) * BPAD + cc]);
            }
#pragma unroll
            for (int mi = 0; mi < 2; mi++)
#pragma unroll
                for (int ni = 0; ni < 8; ni++)
                    mma_tf32(acc[mi][ni], af[mi], bf[ni]);
        }

        if (++stage == NSTAGE) stage = 0;
    }

    // ---------------- epilogue ----------------
    if (!IS_G2) {
#pragma unroll
        for (int mi = 0; mi < 2; mi++) {
            int r0 = m0 + wm * 32 + mi * 16 + g;
#pragma unroll
            for (int ni = 0; ni < 8; ni++) {
                int cc = n0 + wn * 64 + ni * 8 + 2 * tg;
                float2 v0, v1;
                v0.x = rna_tf32(fmaxf(acc[mi][ni][0], 0.f));
                v0.y = rna_tf32(fmaxf(acc[mi][ni][1], 0.f));
                v1.x = rna_tf32(fmaxf(acc[mi][ni][2], 0.f));
                v1.y = rna_tf32(fmaxf(acc[mi][ni][3], 0.f));
                *(float2*)&g_H[(size_t)r0 * FFN + cc]       = v0;
                *(float2*)&g_H[(size_t)(r0 + 8) * FFN + cc] = v1;
            }
        }
    } else {
#pragma unroll
        for (int mi = 0; mi < 2; mi++) {
            int r0 = m0 + wm * 32 + mi * 16 + g;
            int tokA = g_expert_tokens[r0];
            int tokB = g_expert_tokens[r0 + 8];
            float gA = g_gate_slot[r0];
            float gB = g_gate_slot[r0 + 8];
#pragma unroll
            for (int ni = 0; ni < 8; ni++) {
                int cc = n0 + wn * 64 + ni * 8 + 2 * tg;
                if (tokA >= 0) {
                    float2 v; v.x = gA * acc[mi][ni][0]; v.y = gA * acc[mi][ni][1];
                    *(float2*)&OUT[(size_t)tokA * MDIM + cc] = v;
                }
                if (tokB >= 0) {
                    float2 v; v.x = gB * acc[mi][ni][2]; v.y = gB * acc[mi][ni][3];
                    *(float2*)&OUT[(size_t)tokB * MDIM + cc] = v;
                }
            }
        }
    }
}

// ---------------- K5: zero dropped-token rows ----------------
__global__ void zero_dropped_kernel(float* __restrict__ out) {
    int s = blockIdx.x;
    if (g_slot_of_token[s] < 0) {
        float4 z = make_float4(0.f, 0.f, 0.f, 0.f);
        ((float4*)(out + (size_t)s * MDIM))[threadIdx.x] = z;
    }
}

// ---------------- launch ----------------
extern "C" void kernel_launch(void* const* d_in, const int* in_sizes, int n_in,
                              void* d_out, int out_size) {
    const float* x  = (const float*)d_in[0];
    const float* wg = (const float*)d_in[1];
    const float* w1 = (const float*)d_in[2];
    const float* w2 = (const float*)d_in[3];
    float* out = (float*)d_out;

    static bool attr_done = false;
    if (!attr_done) {
        cudaFuncSetAttribute(mma_gemm<MDIM, FFN,  false>,
                             cudaFuncAttributeMaxDynamicSharedMemorySize, GEMM_SMEM);
        cudaFuncSetAttribute(mma_gemm<FFN,  MDIM, true>,
                             cudaFuncAttributeMaxDynamicSharedMemorySize, GEMM_SMEM);
        attr_done = true;
    }

    gate_kernel<<<S_TOK / 8, 256>>>(x, wg);
    scan_kernel<<<NEXP, 1024>>>();

    mma_gemm<MDIM, FFN,  false><<<dim3(FFN / BN,  (NEXP * CAP) / BM), 256, GEMM_SMEM>>>(x, w1, nullptr);
    mma_gemm<FFN,  MDIM, true ><<<dim3(MDIM / BN, (NEXP * CAP) / BM), 256, GEMM_SMEM>>>(x, w2, out);

    zero_dropped_kernel<<<S_TOK, 256>>>(out);
}

// round 6
// speedup vs baseline: 5.7821x; 1.0350x over previous
#include <cuda_runtime.h>
#include <cstdint>
#include <cstddef>

// ---------------- problem constants ----------------
#define S_TOK   8192
#define MDIM    1024
#define NEXP    8
#define FFN     4096
#define CAP     1024

// ---------------- device scratch ----------------
__device__ int   g_expert_of_token[S_TOK];
__device__ float g_gate_of_token[S_TOK];
__device__ int   g_slot_of_token[S_TOK];
__device__ int   g_expert_tokens[NEXP * CAP];
__device__ float g_gate_slot[NEXP * CAP];
__device__ float g_H[(size_t)NEXP * CAP * FFN];   // hidden (tf32-rounded at write)

// ---------------- helpers ----------------
__device__ __forceinline__ uint32_t smem_u32(const void* p) {
    uint32_t a;
    asm("{ .reg .u64 t; cvta.to.shared.u64 t, %1; cvt.u32.u64 %0, t; }" : "=r"(a) : "l"(p));
    return a;
}
__device__ __forceinline__ float rna_tf32(float x) {
    uint32_t u;
    asm("cvt.rna.tf32.f32 %0, %1;" : "=r"(u) : "f"(x));
    return __uint_as_float(u);
}
__device__ __forceinline__ uint32_t rna_tf32_u(float x) {
    uint32_t u;
    asm("cvt.rna.tf32.f32 %0, %1;" : "=r"(u) : "f"(x));
    return u;
}
__device__ __forceinline__ void mma_tf32(float* c, const uint32_t* a, const uint32_t* b) {
    asm volatile(
        "mma.sync.aligned.m16n8k8.row.col.f32.tf32.tf32.f32 "
        "{%0,%1,%2,%3}, {%4,%5,%6,%7}, {%8,%9}, {%0,%1,%2,%3};"
        : "+f"(c[0]), "+f"(c[1]), "+f"(c[2]), "+f"(c[3])
        : "r"(a[0]), "r"(a[1]), "r"(a[2]), "r"(a[3]), "r"(b[0]), "r"(b[1]));
}
__device__ __forceinline__ void cp16(uint32_t dst, const float* src) {
    asm volatile("cp.async.cg.shared.global [%0], [%1], 16;" :: "r"(dst), "l"(src));
}
__device__ __forceinline__ void cp16_zero(uint32_t dst, const float* src) {
    asm volatile("cp.async.cg.shared.global [%0], [%1], 16, 0;" :: "r"(dst), "l"(src));
}

// ---------------- K1: gating ----------------
__global__ void gate_kernel(const float* __restrict__ x, const float* __restrict__ wg) {
    __shared__ float shw[NEXP][MDIM];
    int tid = threadIdx.x;
    for (int idx = tid; idx < MDIM * NEXP; idx += 256) {
        int k = idx >> 3, e = idx & 7;
        shw[e][k] = wg[idx];
    }
    __syncthreads();

    int warp = tid >> 5, lane = tid & 31;
    int s = blockIdx.x * 8 + warp;
    const float* xr = x + (size_t)s * MDIM;

    float acc[NEXP];
#pragma unroll
    for (int e = 0; e < NEXP; e++) acc[e] = 0.f;
#pragma unroll
    for (int i = 0; i < 8; i++) {
        float4 xv = *(const float4*)(xr + i * 128 + lane * 4);
#pragma unroll
        for (int e = 0; e < NEXP; e++) {
            float4 wv = *(const float4*)&shw[e][i * 128 + lane * 4];
            acc[e] += xv.x * wv.x + xv.y * wv.y + xv.z * wv.z + xv.w * wv.w;
        }
    }
#pragma unroll
    for (int e = 0; e < NEXP; e++) {
#pragma unroll
        for (int off = 16; off; off >>= 1)
            acc[e] += __shfl_xor_sync(0xffffffffu, acc[e], off);
    }
    if (lane == 0) {
        float best = acc[0]; int bi = 0;
#pragma unroll
        for (int e = 1; e < NEXP; e++)
            if (acc[e] > best) { best = acc[e]; bi = e; }
        float sum = 0.f;
#pragma unroll
        for (int e = 0; e < NEXP; e++) sum += __expf(acc[e] - best);
        g_expert_of_token[s] = bi;
        g_gate_of_token[s]   = 1.0f / sum;
        g_slot_of_token[s]   = -1;
    }
}

// ---------------- K2: per-expert rank scan ----------------
__global__ void scan_kernel() {
    int e = blockIdx.x;
    int t = threadIdx.x;
    g_expert_tokens[e * CAP + t] = -1;
    g_gate_slot[e * CAP + t] = 0.f;
    __syncthreads();

    int base = t * 8;
    int cnt = 0;
    int loc[8];
#pragma unroll
    for (int j = 0; j < 8; j++) {
        loc[j] = cnt;
        if (g_expert_of_token[base + j] == e) cnt++;
    }
    __shared__ int sh[1024];
    sh[t] = cnt;
    __syncthreads();
    for (int off = 1; off < 1024; off <<= 1) {
        int v = (t >= off) ? sh[t - off] : 0;
        __syncthreads();
        sh[t] += v;
        __syncthreads();
    }
    int excl = sh[t] - cnt;
#pragma unroll
    for (int j = 0; j < 8; j++) {
        int s = base + j;
        if (g_expert_of_token[s] == e) {
            int c = excl + loc[j];
            if (c < CAP) {
                g_expert_tokens[e * CAP + c] = s;
                g_gate_slot[e * CAP + c]     = g_gate_of_token[s];
                g_slot_of_token[s]           = c;
            }
        }
    }
}

// ---------------- K3: tf32 mma.sync GEMM ----------------
// C tile 256x128, BK=32, 8 warps (4 M x 2 N), warp tile 64x64.
// 3-stage cp.async ring in dynamic SMEM, one __syncthreads per 32-wide k-chunk.
// A[m,k] SMEM [256][36] padded, B[k,n] SMEM [32][136] padded (conflict-free).
#define BM 256
#define BN 128
#define BK 32
#define APAD 36
#define BPAD 136
#define NSTAGE 3
#define A_FLOATS (BM * APAD)                         // 9216
#define STAGE_B  ((BM * APAD + BK * BPAD) * 4)       // 54272 bytes
#define GEMM_SMEM (NSTAGE * STAGE_B)                 // 162816

template<int K_TOTAL, int NDIM, bool IS_G2>
__global__ void __launch_bounds__(256, 1) mma_gemm(const float* __restrict__ Xin,
                                                   const float* __restrict__ W,
                                                   float* __restrict__ OUT) {
    constexpr int CITER = K_TOTAL / BK;
    extern __shared__ char smraw[];
    uint32_t sbase = smem_u32(smraw);

    int tid = threadIdx.x;
    int wid = tid >> 5, lane = tid & 31;
    int wm = wid & 3, wn = wid >> 2;
    int g = lane >> 2, tg = lane & 3;

    int m0 = blockIdx.y * BM;
    int n0 = blockIdx.x * BN;
    int e  = m0 >> 10;

    const float* Bw = W + (size_t)e * ((size_t)MDIM * FFN);

    // --- A loads: 2048 chunks of 16B (256 rows x 8 chunks), 8 per thread ---
    const float* srcA[8];
    uint32_t offA[8];
#pragma unroll
    for (int i = 0; i < 8; i++) {
        int idx = tid + i * 256;
        int r = idx >> 3, ch = idx & 7;
        offA[i] = (uint32_t)(r * APAD + ch * 4) * 4u;
        const float* p;
        if (IS_G2) p = &g_H[(size_t)(m0 + r) * FFN];
        else {
            int tok = g_expert_tokens[m0 + r];
            p = (tok >= 0) ? (Xin + (size_t)tok * MDIM) : nullptr;
        }
        srcA[i] = p ? (p + ch * 4) : nullptr;
    }
    // --- B loads: 1024 chunks (32 rows x 32 chunks), 4 per thread ---
    const float* srcB[4];
    uint32_t offB[4];
#pragma unroll
    for (int i = 0; i < 4; i++) {
        int idx = tid + i * 256;
        int r = idx >> 5, ch = idx & 31;
        offB[i] = (uint32_t)(A_FLOATS + r * BPAD + ch * 4) * 4u;
        srcB[i] = Bw + (size_t)r * NDIM + n0 + ch * 4;
    }

    auto load_stage = [&](int s, int k0) {
        uint32_t sb = sbase + (uint32_t)s * STAGE_B;
#pragma unroll
        for (int i = 0; i < 8; i++) {
            if (srcA[i]) cp16(sb + offA[i], srcA[i] + k0);
            else         cp16_zero(sb + offA[i], Bw);
        }
#pragma unroll
        for (int i = 0; i < 4; i++)
            cp16(sb + offB[i], srcB[i] + (size_t)k0 * NDIM);
        asm volatile("cp.async.commit_group;" ::: "memory");
    };

    load_stage(0, 0);
    load_stage(1, BK);

    float acc[4][8][4];
#pragma unroll
    for (int mi = 0; mi < 4; mi++)
#pragma unroll
        for (int ni = 0; ni < 8; ni++)
#pragma unroll
            for (int q = 0; q < 4; q++) acc[mi][ni][q] = 0.f;

    int stage = 0;
    for (int c = 0; c < CITER; c++) {
        if (c + 1 < CITER) asm volatile("cp.async.wait_group 1;" ::: "memory");
        else               asm volatile("cp.async.wait_group 0;" ::: "memory");
        __syncthreads();

        int pf = stage + 2; if (pf >= NSTAGE) pf -= NSTAGE;
        if (c + 2 < CITER) load_stage(pf, (c + 2) * BK);

        const float* As = (const float*)(smraw + (size_t)stage * STAGE_B);
        const float* Bs = As + A_FLOATS;

#pragma unroll
        for (int kk = 0; kk < 4; kk++) {
            int kb = kk * 8;
            uint32_t af[4][4];
#pragma unroll
            for (int mi = 0; mi < 4; mi++) {
                int r = wm * 64 + mi * 16 + g;
                float a0 = As[r * APAD + kb + tg];
                float a1 = As[(r + 8) * APAD + kb + tg];
                float a2 = As[r * APAD + kb + tg + 4];
                float a3 = As[(r + 8) * APAD + kb + tg + 4];
                if (!IS_G2) {   // x raw fp32 -> round; g_H pre-rounded
                    af[mi][0] = rna_tf32_u(a0); af[mi][1] = rna_tf32_u(a1);
                    af[mi][2] = rna_tf32_u(a2); af[mi][3] = rna_tf32_u(a3);
                } else {
                    af[mi][0] = __float_as_uint(a0); af[mi][1] = __float_as_uint(a1);
                    af[mi][2] = __float_as_uint(a2); af[mi][3] = __float_as_uint(a3);
                }
            }
            uint32_t bf[8][2];
#pragma unroll
            for (int ni = 0; ni < 8; ni++) {
                int cc = wn * 64 + ni * 8 + g;
                bf[ni][0] = rna_tf32_u(Bs[(kb + tg) * BPAD + cc]);
                bf[ni][1] = rna_tf32_u(Bs[(kb + tg + 4) * BPAD + cc]);
            }
#pragma unroll
            for (int mi = 0; mi < 4; mi++)
#pragma unroll
                for (int ni = 0; ni < 8; ni++)
                    mma_tf32(acc[mi][ni], af[mi], bf[ni]);
        }

        if (++stage == NSTAGE) stage = 0;
    }

    // ---------------- epilogue ----------------
    if (!IS_G2) {
#pragma unroll
        for (int mi = 0; mi < 4; mi++) {
            int r0 = m0 + wm * 64 + mi * 16 + g;
#pragma unroll
            for (int ni = 0; ni < 8; ni++) {
                int cc = n0 + wn * 64 + ni * 8 + 2 * tg;
                float2 v0, v1;
                v0.x = rna_tf32(fmaxf(acc[mi][ni][0], 0.f));
                v0.y = rna_tf32(fmaxf(acc[mi][ni][1], 0.f));
                v1.x = rna_tf32(fmaxf(acc[mi][ni][2], 0.f));
                v1.y = rna_tf32(fmaxf(acc[mi][ni][3], 0.f));
                *(float2*)&g_H[(size_t)r0 * FFN + cc]       = v0;
                *(float2*)&g_H[(size_t)(r0 + 8) * FFN + cc] = v1;
            }
        }
    } else {
#pragma unroll
        for (int mi = 0; mi < 4; mi++) {
            int r0 = m0 + wm * 64 + mi * 16 + g;
            int tokA = g_expert_tokens[r0];
            int tokB = g_expert_tokens[r0 + 8];
            float gA = g_gate_slot[r0];
            float gB = g_gate_slot[r0 + 8];
#pragma unroll
            for (int ni = 0; ni < 8; ni++) {
                int cc = n0 + wn * 64 + ni * 8 + 2 * tg;
                if (tokA >= 0) {
                    float2 v; v.x = gA * acc[mi][ni][0]; v.y = gA * acc[mi][ni][1];
                    *(float2*)&OUT[(size_t)tokA * MDIM + cc] = v;
                }
                if (tokB >= 0) {
                    float2 v; v.x = gB * acc[mi][ni][2]; v.y = gB * acc[mi][ni][3];
                    *(float2*)&OUT[(size_t)tokB * MDIM + cc] = v;
                }
            }
        }
    }
}

// ---------------- K5: zero dropped-token rows ----------------
__global__ void zero_dropped_kernel(float* __restrict__ out) {
    int s = blockIdx.x;
    if (g_slot_of_token[s] < 0) {
        float4 z = make_float4(0.f, 0.f, 0.f, 0.f);
        ((float4*)(out + (size_t)s * MDIM))[threadIdx.x] = z;
    }
}

// ---------------- launch ----------------
extern "C" void kernel_launch(void* const* d_in, const int* in_sizes, int n_in,
                              void* d_out, int out_size) {
    const float* x  = (const float*)d_in[0];
    const float* wg = (const float*)d_in[1];
    const float* w1 = (const float*)d_in[2];
    const float* w2 = (const float*)d_in[3];
    float* out = (float*)d_out;

    static bool attr_done = false;
    if (!attr_done) {
        cudaFuncSetAttribute(mma_gemm<MDIM, FFN,  false>,
                             cudaFuncAttributeMaxDynamicSharedMemorySize, GEMM_SMEM);
        cudaFuncSetAttribute(mma_gemm<FFN,  MDIM, true>,
                             cudaFuncAttributeMaxDynamicSharedMemorySize, GEMM_SMEM);
        attr_done = true;
    }

    gate_kernel<<<S_TOK / 8, 256>>>(x, wg);
    scan_kernel<<<NEXP, 1024>>>();

    mma_gemm<MDIM, FFN,  false><<<dim3(FFN / BN,  (NEXP * CAP) / BM), 256, GEMM_SMEM>>>(x, w1, nullptr);
    mma_gemm<FFN,  MDIM, true ><<<dim3(MDIM / BN, (NEXP * CAP) / BM), 256, GEMM_SMEM>>>(x, w2, out);

    zero_dropped_kernel<<<S_TOK, 256>>>(out);
}

// round 7
// speedup vs baseline: 5.9083x; 1.0218x over previous
#include <cuda_runtime.h>
#include <cstdint>
#include <cstddef>

// ---------------- problem constants ----------------
#define S_TOK   8192
#define MDIM    1024
#define NEXP    8
#define FFN     4096
#define CAP     1024

// ---------------- device scratch ----------------
__device__ int   g_expert_of_token[S_TOK];
__device__ float g_gate_of_token[S_TOK];
__device__ int   g_slot_of_token[S_TOK];
__device__ int   g_expert_tokens[NEXP * CAP];
__device__ float g_gate_slot[NEXP * CAP];
__device__ float g_H[(size_t)NEXP * CAP * FFN];   // hidden (tf32-rounded at write)

// ---------------- helpers ----------------
__device__ __forceinline__ uint32_t smem_u32(const void* p) {
    uint32_t a;
    asm("{ .reg .u64 t; cvta.to.shared.u64 t, %1; cvt.u32.u64 %0, t; }" : "=r"(a) : "l"(p));
    return a;
}
__device__ __forceinline__ float rna_tf32(float x) {
    uint32_t u;
    asm("cvt.rna.tf32.f32 %0, %1;" : "=r"(u) : "f"(x));
    return __uint_as_float(u);
}
__device__ __forceinline__ uint32_t rna_tf32_u(float x) {
    uint32_t u;
    asm("cvt.rna.tf32.f32 %0, %1;" : "=r"(u) : "f"(x));
    return u;
}
__device__ __forceinline__ void mma_tf32(float* c, const uint32_t* a, const uint32_t* b) {
    asm volatile(
        "mma.sync.aligned.m16n8k8.row.col.f32.tf32.tf32.f32 "
        "{%0,%1,%2,%3}, {%4,%5,%6,%7}, {%8,%9}, {%0,%1,%2,%3};"
        : "+f"(c[0]), "+f"(c[1]), "+f"(c[2]), "+f"(c[3])
        : "r"(a[0]), "r"(a[1]), "r"(a[2]), "r"(a[3]), "r"(b[0]), "r"(b[1]));
}
__device__ __forceinline__ void cp16(uint32_t dst, const float* src) {
    asm volatile("cp.async.cg.shared.global [%0], [%1], 16;" :: "r"(dst), "l"(src));
}
__device__ __forceinline__ void cp16_zero(uint32_t dst, const float* src) {
    asm volatile("cp.async.cg.shared.global [%0], [%1], 16, 0;" :: "r"(dst), "l"(src));
}

// ---------------- K1: gating ----------------
__global__ void gate_kernel(const float* __restrict__ x, const float* __restrict__ wg) {
    __shared__ float shw[NEXP][MDIM];
    int tid = threadIdx.x;
    for (int idx = tid; idx < MDIM * NEXP; idx += 256) {
        int k = idx >> 3, e = idx & 7;
        shw[e][k] = wg[idx];
    }
    __syncthreads();

    int warp = tid >> 5, lane = tid & 31;
    int s = blockIdx.x * 8 + warp;
    const float* xr = x + (size_t)s * MDIM;

    float acc[NEXP];
#pragma unroll
    for (int e = 0; e < NEXP; e++) acc[e] = 0.f;
#pragma unroll
    for (int i = 0; i < 8; i++) {
        float4 xv = *(const float4*)(xr + i * 128 + lane * 4);
#pragma unroll
        for (int e = 0; e < NEXP; e++) {
            float4 wv = *(const float4*)&shw[e][i * 128 + lane * 4];
            acc[e] += xv.x * wv.x + xv.y * wv.y + xv.z * wv.z + xv.w * wv.w;
        }
    }
#pragma unroll
    for (int e = 0; e < NEXP; e++) {
#pragma unroll
        for (int off = 16; off; off >>= 1)
            acc[e] += __shfl_xor_sync(0xffffffffu, acc[e], off);
    }
    if (lane == 0) {
        float best = acc[0]; int bi = 0;
#pragma unroll
        for (int e = 1; e < NEXP; e++)
            if (acc[e] > best) { best = acc[e]; bi = e; }
        float sum = 0.f;
#pragma unroll
        for (int e = 0; e < NEXP; e++) sum += __expf(acc[e] - best);
        g_expert_of_token[s] = bi;
        g_gate_of_token[s]   = 1.0f / sum;
        g_slot_of_token[s]   = -1;
    }
}

// ---------------- K2: per-expert rank scan ----------------
__global__ void scan_kernel() {
    int e = blockIdx.x;
    int t = threadIdx.x;
    g_expert_tokens[e * CAP + t] = -1;
    g_gate_slot[e * CAP + t] = 0.f;
    __syncthreads();

    int base = t * 8;
    int cnt = 0;
    int loc[8];
#pragma unroll
    for (int j = 0; j < 8; j++) {
        loc[j] = cnt;
        if (g_expert_of_token[base + j] == e) cnt++;
    }
    __shared__ int sh[1024];
    sh[t] = cnt;
    __syncthreads();
    for (int off = 1; off < 1024; off <<= 1) {
        int v = (t >= off) ? sh[t - off] : 0;
        __syncthreads();
        sh[t] += v;
        __syncthreads();
    }
    int excl = sh[t] - cnt;
#pragma unroll
    for (int j = 0; j < 8; j++) {
        int s = base + j;
        if (g_expert_of_token[s] == e) {
            int c = excl + loc[j];
            if (c < CAP) {
                g_expert_tokens[e * CAP + c] = s;
                g_gate_slot[e * CAP + c]     = g_gate_of_token[s];
                g_slot_of_token[s]           = c;
            }
        }
    }
}

// ---------------- K3: tf32 mma.sync GEMM ----------------
// C tile 256x128, BK=64, 8 warps (4 M x 2 N), warp tile 64x64.
// 2-stage cp.async double buffer, one __syncthreads per 64-wide k-chunk.
// A[m,k] SMEM [256][68] padded, B[k,n] SMEM [64][136] padded (conflict-free).
#define BM 256
#define BN 128
#define BK 64
#define APAD 68
#define BPAD 136
#define NSTAGE 2
#define A_FLOATS (BM * APAD)                         // 17408
#define STAGE_B  ((BM * APAD + BK * BPAD) * 4)       // 104448 bytes
#define GEMM_SMEM (NSTAGE * STAGE_B)                 // 208896

template<int K_TOTAL, int NDIM, bool IS_G2>
__global__ void __launch_bounds__(256, 1) mma_gemm(const float* __restrict__ Xin,
                                                   const float* __restrict__ W,
                                                   float* __restrict__ OUT) {
    constexpr int CITER = K_TOTAL / BK;
    extern __shared__ char smraw[];
    uint32_t sbase = smem_u32(smraw);

    int tid = threadIdx.x;
    int wid = tid >> 5, lane = tid & 31;
    int wm = wid & 3, wn = wid >> 2;
    int g = lane >> 2, tg = lane & 3;

    int m0 = blockIdx.y * BM;
    int n0 = blockIdx.x * BN;
    int e  = m0 >> 10;

    const float* Bw = W + (size_t)e * ((size_t)MDIM * FFN);

    // --- A loads: 4096 chunks of 16B (256 rows x 16 chunks), 16 per thread ---
    const float* srcA[16];
    uint32_t offA[16];
#pragma unroll
    for (int i = 0; i < 16; i++) {
        int idx = tid + i * 256;
        int r = idx >> 4, ch = idx & 15;
        offA[i] = (uint32_t)(r * APAD + ch * 4) * 4u;
        const float* p;
        if (IS_G2) p = &g_H[(size_t)(m0 + r) * FFN];
        else {
            int tok = g_expert_tokens[m0 + r];
            p = (tok >= 0) ? (Xin + (size_t)tok * MDIM) : nullptr;
        }
        srcA[i] = p ? (p + ch * 4) : nullptr;
    }
    // --- B loads: 2048 chunks (64 rows x 32 chunks), 8 per thread ---
    const float* srcB[8];
    uint32_t offB[8];
#pragma unroll
    for (int i = 0; i < 8; i++) {
        int idx = tid + i * 256;
        int r = idx >> 5, ch = idx & 31;
        offB[i] = (uint32_t)(A_FLOATS + r * BPAD + ch * 4) * 4u;
        srcB[i] = Bw + (size_t)r * NDIM + n0 + ch * 4;
    }

    auto load_stage = [&](int s, int k0) {
        uint32_t sb = sbase + (uint32_t)s * STAGE_B;
#pragma unroll
        for (int i = 0; i < 16; i++) {
            if (srcA[i]) cp16(sb + offA[i], srcA[i] + k0);
            else         cp16_zero(sb + offA[i], Bw);
        }
#pragma unroll
        for (int i = 0; i < 8; i++)
            cp16(sb + offB[i], srcB[i] + (size_t)k0 * NDIM);
        asm volatile("cp.async.commit_group;" ::: "memory");
    };

    load_stage(0, 0);

    float acc[4][8][4];
#pragma unroll
    for (int mi = 0; mi < 4; mi++)
#pragma unroll
        for (int ni = 0; ni < 8; ni++)
#pragma unroll
            for (int q = 0; q < 4; q++) acc[mi][ni][q] = 0.f;

    for (int c = 0; c < CITER; c++) {
        int s = c & 1;
        asm volatile("cp.async.wait_group 0;" ::: "memory");  // chunk c landed
        __syncthreads();                                      // all warps done with buf c-1
        if (c + 1 < CITER) load_stage(s ^ 1, (c + 1) * BK);   // overlap with compute of c

        const float* As = (const float*)(smraw + (size_t)s * STAGE_B);
        const float* Bs = As + A_FLOATS;

        // B-fragment software pipeline: load bf(kk+1) while issuing MMAs of kk
        uint32_t bfb[2][8][2];
        {
#pragma unroll
            for (int ni = 0; ni < 8; ni++) {
                int cc = wn * 64 + ni * 8 + g;
                bfb[0][ni][0] = rna_tf32_u(Bs[tg * BPAD + cc]);
                bfb[0][ni][1] = rna_tf32_u(Bs[(tg + 4) * BPAD + cc]);
            }
        }
#pragma unroll
        for (int kk = 0; kk < 8; kk++) {
            int kb = kk * 8;
            int cur = kk & 1;
            if (kk + 1 < 8) {
                int kb2 = kb + 8;
#pragma unroll
                for (int ni = 0; ni < 8; ni++) {
                    int cc = wn * 64 + ni * 8 + g;
                    bfb[cur ^ 1][ni][0] = rna_tf32_u(Bs[(kb2 + tg) * BPAD + cc]);
                    bfb[cur ^ 1][ni][1] = rna_tf32_u(Bs[(kb2 + tg + 4) * BPAD + cc]);
                }
            }
            uint32_t af[4][4];
#pragma unroll
            for (int mi = 0; mi < 4; mi++) {
                int r = wm * 64 + mi * 16 + g;
                float a0 = As[r * APAD + kb + tg];
                float a1 = As[(r + 8) * APAD + kb + tg];
                float a2 = As[r * APAD + kb + tg + 4];
                float a3 = As[(r + 8) * APAD + kb + tg + 4];
                if (!IS_G2) {   // x raw fp32 -> round; g_H pre-rounded
                    af[mi][0] = rna_tf32_u(a0); af[mi][1] = rna_tf32_u(a1);
                    af[mi][2] = rna_tf32_u(a2); af[mi][3] = rna_tf32_u(a3);
                } else {
                    af[mi][0] = __float_as_uint(a0); af[mi][1] = __float_as_uint(a1);
                    af[mi][2] = __float_as_uint(a2); af[mi][3] = __float_as_uint(a3);
                }
            }
#pragma unroll
            for (int mi = 0; mi < 4; mi++)
#pragma unroll
                for (int ni = 0; ni < 8; ni++)
                    mma_tf32(acc[mi][ni], af[mi], bfb[cur][ni]);
        }
    }

    // ---------------- epilogue ----------------
    if (!IS_G2) {
#pragma unroll
        for (int mi = 0; mi < 4; mi++) {
            int r0 = m0 + wm * 64 + mi * 16 + g;
#pragma unroll
            for (int ni = 0; ni < 8; ni++) {
                int cc = n0 + wn * 64 + ni * 8 + 2 * tg;
                float2 v0, v1;
                v0.x = rna_tf32(fmaxf(acc[mi][ni][0], 0.f));
                v0.y = rna_tf32(fmaxf(acc[mi][ni][1], 0.f));
                v1.x = rna_tf32(fmaxf(acc[mi][ni][2], 0.f));
                v1.y = rna_tf32(fmaxf(acc[mi][ni][3], 0.f));
                *(float2*)&g_H[(size_t)r0 * FFN + cc]       = v0;
                *(float2*)&g_H[(size_t)(r0 + 8) * FFN + cc] = v1;
            }
        }
    } else {
#pragma unroll
        for (int mi = 0; mi < 4; mi++) {
            int r0 = m0 + wm * 64 + mi * 16 + g;
            int tokA = g_expert_tokens[r0];
            int tokB = g_expert_tokens[r0 + 8];
            float gA = g_gate_slot[r0];
            float gB = g_gate_slot[r0 + 8];
#pragma unroll
            for (int ni = 0; ni < 8; ni++) {
                int cc = n0 + wn * 64 + ni * 8 + 2 * tg;
                if (tokA >= 0) {
                    float2 v; v.x = gA * acc[mi][ni][0]; v.y = gA * acc[mi][ni][1];
                    *(float2*)&OUT[(size_t)tokA * MDIM + cc] = v;
                }
                if (tokB >= 0) {
                    float2 v; v.x = gB * acc[mi][ni][2]; v.y = gB * acc[mi][ni][3];
                    *(float2*)&OUT[(size_t)tokB * MDIM + cc] = v;
                }
            }
        }
    }
}

// ---------------- K5: zero dropped-token rows ----------------
__global__ void zero_dropped_kernel(float* __restrict__ out) {
    int s = blockIdx.x;
    if (g_slot_of_token[s] < 0) {
        float4 z = make_float4(0.f, 0.f, 0.f, 0.f);
        ((float4*)(out + (size_t)s * MDIM))[threadIdx.x] = z;
    }
}

// ---------------- launch ----------------
extern "C" void kernel_launch(void* const* d_in, const int* in_sizes, int n_in,
                              void* d_out, int out_size) {
    const float* x  = (const float*)d_in[0];
    const float* wg = (const float*)d_in[1];
    const float* w1 = (const float*)d_in[2];
    const float* w2 = (const float*)d_in[3];
    float* out = (float*)d_out;

    static bool attr_done = false;
    if (!attr_done) {
        cudaFuncSetAttribute(mma_gemm<MDIM, FFN,  false>,
                             cudaFuncAttributeMaxDynamicSharedMemorySize, GEMM_SMEM);
        cudaFuncSetAttribute(mma_gemm<FFN,  MDIM, true>,
                             cudaFuncAttributeMaxDynamicSharedMemorySize, GEMM_SMEM);
        attr_done = true;
    }

    gate_kernel<<<S_TOK / 8, 256>>>(x, wg);
    scan_kernel<<<NEXP, 1024>>>();

    mma_gemm<MDIM, FFN,  false><<<dim3(FFN / BN,  (NEXP * CAP) / BM), 256, GEMM_SMEM>>>(x, w1, nullptr);
    mma_gemm<FFN,  MDIM, true ><<<dim3(MDIM / BN, (NEXP * CAP) / BM), 256, GEMM_SMEM>>>(x, w2, out);

    zero_dropped_kernel<<<S_TOK, 256>>>(out);
}